// round 1
// baseline (speedup 1.0000x reference)
#include <cuda_runtime.h>
#include <math.h>

#define Bb 4
#define Nn 20000
#define Uu 64
#define Ff 65
#define Ee 640000
#define NODES (Bb*Nn)
#define ATT_SCALE 0.125f
#define TILE 128

// ---------------- device scratch (static, no runtime alloc) ----------------
__device__ float g_q[NODES*Uu];
__device__ float g_k[NODES*Uu];
__device__ float g_v[NODES*Uu];
__device__ float g_agg[NODES*Uu];
__device__ unsigned char g_mask[NODES];
__device__ int g_cnt[Nn];
__device__ int g_off[Nn];
__device__ int g_cur[Nn];
__device__ int g_eid[Ee];

// ---------------- CSR build ----------------
__global__ void zero_cnt_kernel() {
    int i = blockIdx.x * blockDim.x + threadIdx.x;
    if (i < Nn) g_cnt[i] = 0;
}

__global__ void hist_kernel(const int* __restrict__ edst) {
    int i = blockIdx.x * blockDim.x + threadIdx.x;
    if (i < Ee) atomicAdd(&g_cnt[edst[i]], 1);
}

__global__ void scan_kernel() {
    __shared__ int sp[1024];
    int tid = threadIdx.x;
    int base = tid * 20;
    int s = 0;
    for (int i = 0; i < 20; i++) {
        int idx = base + i;
        if (idx < Nn) s += g_cnt[idx];
    }
    sp[tid] = s;
    __syncthreads();
    for (int d = 1; d < 1024; d <<= 1) {
        int v = (tid >= d) ? sp[tid - d] : 0;
        __syncthreads();
        sp[tid] += v;
        __syncthreads();
    }
    int run = sp[tid] - s;   // exclusive prefix
    for (int i = 0; i < 20; i++) {
        int idx = base + i;
        if (idx < Nn) {
            g_off[idx] = run;
            g_cur[idx] = run;
            run += g_cnt[idx];
        }
    }
}

__global__ void scatter_kernel(const int* __restrict__ edst) {
    int i = blockIdx.x * blockDim.x + threadIdx.x;
    if (i < Ee) {
        int pos = atomicAdd(&g_cur[edst[i]], 1);
        g_eid[pos] = i;
    }
}

// ---------------- QKV projection + mask ----------------
// x = [h(0..63), xin(64)], q/k/v[u] = sum_f x[f]*W[f][u] + b[u]
// block = 256 threads = 4 groups of 64 (u = tid&63); each group does 4 nodes
// (register blocking) -> 16 nodes per chunk.
__global__ void __launch_bounds__(256) qkv_kernel(
    const float* __restrict__ inputs, const float* __restrict__ state,
    const float* __restrict__ Wq, const float* __restrict__ bq,
    const float* __restrict__ Wk, const float* __restrict__ bk,
    const float* __restrict__ Wv, const float* __restrict__ bv)
{
    extern __shared__ float sm[];
    float* sWq = sm;                       // F*U
    float* sWk = sWq + Ff*Uu;              // F*U
    float* sWv = sWk + Ff*Uu;              // F*U
    float* sb  = sWv + Ff*Uu;              // 3*U
    float* sx  = sb + 3*Uu;                // 16 * 66

    for (int i = threadIdx.x; i < Ff*Uu; i += 256) {
        sWq[i] = Wq[i]; sWk[i] = Wk[i]; sWv[i] = Wv[i];
    }
    if (threadIdx.x < Uu) {
        sb[threadIdx.x]        = bq[threadIdx.x];
        sb[threadIdx.x + Uu]   = bk[threadIdx.x];
        sb[threadIdx.x + 2*Uu] = bv[threadIdx.x];
    }
    __syncthreads();

    int u = threadIdx.x & 63;
    int g = threadIdx.x >> 6;
    int ln0 = g * 4;
    int nChunks = (NODES + 15) / 16;

    for (int c = blockIdx.x; c < nChunks; c += gridDim.x) {
        int base = c * 16;
        __syncthreads();
        // stage x rows: 16 x 65 (stride 66)
        for (int i = threadIdx.x; i < 16*Ff; i += 256) {
            int ln = i / Ff, f = i - ln*Ff;
            int node = base + ln;
            float v = 0.f;
            if (node < NODES) {
                int b = node / Nn, n = node - b*Nn;
                v = (f < Uu) ? state[(size_t)b*Nn*Uu + (size_t)n*Uu + f]
                             : inputs[b*Nn + n];
            }
            sx[ln*(Ff+1) + f] = v;
        }
        __syncthreads();
        if (threadIdx.x < 16) {
            int node = base + threadIdx.x;
            if (node < NODES)
                g_mask[node] = (sx[threadIdx.x*(Ff+1) + 58] != 0.f) ? 1 : 0;
        }

        float aq[4] = {0,0,0,0}, ak[4] = {0,0,0,0}, av[4] = {0,0,0,0};
        #pragma unroll 5
        for (int f = 0; f < Ff; f++) {
            float wq = sWq[f*Uu + u];
            float wk = sWk[f*Uu + u];
            float wv = sWv[f*Uu + u];
            #pragma unroll
            for (int j = 0; j < 4; j++) {
                float xv = sx[(ln0 + j)*(Ff+1) + f];
                aq[j] += xv * wq;
                ak[j] += xv * wk;
                av[j] += xv * wv;
            }
        }
        #pragma unroll
        for (int j = 0; j < 4; j++) {
            int node = base + ln0 + j;
            if (node < NODES) {
                size_t idx = (size_t)node*Uu + u;
                g_q[idx] = aq[j] + sb[u];
                g_k[idx] = ak[j] + sb[Uu + u];
                g_v[idx] = av[j] + sb[2*Uu + u];
            }
        }
    }
}

// ---------------- attention per (b, dst) ----------------
// Softmax without max-subtraction (shift-invariant; scores are O(+-8)).
// Phase 1: warp-per-edge score+exp into smem.  Phase 2: u-threads stream
// coalesced v rows, accumulate numerator & denominator in registers.
__global__ void __launch_bounds__(128) attn_kernel(const int* __restrict__ esrc) {
    int id = blockIdx.x;
    int b = id / Nn;
    int n = id - b * Nn;
    if (!g_mask[b*Nn + n]) return;

    __shared__ float sq[Uu];
    __shared__ float sw[TILE];
    __shared__ int   ssrc[TILE];
    __shared__ float sacc[128];
    __shared__ float sden[128];

    int tid  = threadIdx.x;
    int lane = tid & 31;
    int warp = tid >> 5;
    int u    = tid & 63;
    int half = tid >> 6;

    size_t rowbase = (size_t)(b*Nn + n) * Uu;
    if (tid < Uu) sq[tid] = g_q[rowbase + tid];

    int off = g_off[n];
    int deg = g_cnt[n];
    const float* kbase = g_k + (size_t)b*Nn*Uu;
    const float* vbase = g_v + (size_t)b*Nn*Uu;
    const unsigned char* mk = g_mask + b*Nn;

    float acc = 0.f, den = 0.f;

    for (int t0 = 0; t0 < deg; t0 += TILE) {
        int tl = min(TILE, deg - t0);
        __syncthreads();
        // phase 1: scores
        for (int t = warp; t < tl; t += 4) {
            int e = g_eid[off + t0 + t];
            int src = esrc[e];
            const float* krow = kbase + (size_t)src * Uu;
            float p = krow[lane*2] * sq[lane*2] + krow[lane*2+1] * sq[lane*2+1];
            #pragma unroll
            for (int d = 16; d; d >>= 1) p += __shfl_xor_sync(0xffffffffu, p, d);
            if (lane == 0) {
                sw[t]   = mk[src] ? __expf(p * ATT_SCALE) : 0.f;
                ssrc[t] = src;
            }
        }
        __syncthreads();
        // phase 2: weighted V accumulate (coalesced across u)
        for (int t = half; t < tl; t += 2) {
            float w = sw[t];
            int src = ssrc[t];
            den += w;
            acc += w * vbase[(size_t)src * Uu + u];
        }
    }

    sacc[tid] = acc;
    sden[tid] = den;
    __syncthreads();
    if (tid < Uu) {
        float num = sacc[tid] + sacc[tid + 64];
        float dd  = sden[tid] + sden[tid + 64];
        float a = (dd > 0.f) ? num / fmaxf(dd, 1e-16f) : 0.f;
        g_agg[rowbase + tid] = a;
    }
}

// ---------------- fused GRU epilogue ----------------
__global__ void __launch_bounds__(256) gru_kernel(
    const float* __restrict__ inputs, const float* __restrict__ state,
    const float* __restrict__ Ws, const float* __restrict__ bs,
    const float* __restrict__ W1, const float* __restrict__ b1,
    const float* __restrict__ W2, const float* __restrict__ b2,
    float* __restrict__ out)
{
    extern __shared__ float sm[];
    float* sWs = sm;                         // F*U
    float* sW1 = sWs + Ff*Uu;                // F*128
    float* sW2 = sW1 + Ff*128;               // F*U
    float* sbs = sW2 + Ff*Uu;                // U
    float* sb1 = sbs + Uu;                   // 128
    float* sb2 = sb1 + 128;                  // U
    float* sx   = sb2 + Uu;                  // 16*66  x = [h, xin]
    float* sh2  = sx  + 16*(Ff+1);           // 16*66  cat1 = [xin, h2]
    float* srh2 = sh2 + 16*(Ff+1);           // 16*66  [xin, reset*h2]

    for (int i = threadIdx.x; i < Ff*Uu; i += 256)  sWs[i] = Ws[i];
    for (int i = threadIdx.x; i < Ff*128; i += 256) sW1[i] = W1[i];
    for (int i = threadIdx.x; i < Ff*Uu; i += 256)  sW2[i] = W2[i];
    if (threadIdx.x < Uu)  sbs[threadIdx.x] = bs[threadIdx.x];
    if (threadIdx.x < 128) sb1[threadIdx.x] = b1[threadIdx.x];
    if (threadIdx.x < Uu)  sb2[threadIdx.x] = b2[threadIdx.x];
    __syncthreads();

    int u = threadIdx.x & 63;
    int g = threadIdx.x >> 6;
    int ln0 = g * 4;
    int nChunks = (NODES + 15) / 16;

    for (int c = blockIdx.x; c < nChunks; c += gridDim.x) {
        int base = c * 16;
        __syncthreads();
        for (int i = threadIdx.x; i < 16*Ff; i += 256) {
            int ln = i / Ff, f = i - ln*Ff;
            int node = base + ln;
            float v = 0.f;
            if (node < NODES) {
                int b = node / Nn, n = node - b*Nn;
                v = (f < Uu) ? state[(size_t)b*Nn*Uu + (size_t)n*Uu + f]
                             : inputs[b*Nn + n];
            }
            sx[ln*(Ff+1) + f] = v;
        }
        __syncthreads();

        // s = x @ Ws + bs
        float sacc[4] = {0,0,0,0};
        #pragma unroll 5
        for (int f = 0; f < Ff; f++) {
            float w = sWs[f*Uu + u];
            #pragma unroll
            for (int j = 0; j < 4; j++)
                sacc[j] += sx[(ln0 + j)*(Ff+1) + f] * w;
        }

        float h2v[4], xinv[4];
        bool nodeok[4];
        #pragma unroll
        for (int j = 0; j < 4; j++) {
            int ln = ln0 + j;
            int node = base + ln;
            nodeok[j] = (node < NODES);
            float hv  = sx[ln*(Ff+1) + u];
            xinv[j]   = sx[ln*(Ff+1) + Uu];
            bool msk  = (sx[ln*(Ff+1) + 58] != 0.f);
            float av  = nodeok[j] ? g_agg[(size_t)(nodeok[j] ? node : 0)*Uu + u] : 0.f;
            float h2  = msk ? (av + sacc[j] + sbs[u]) : hv;
            h2v[j] = h2;
            sh2[ln*(Ff+1) + 1 + u] = h2;
            if (u == 0) sh2[ln*(Ff+1) + 0] = xinv[j];
        }
        __syncthreads();

        // value = sigmoid(cat1 @ W1 + b1): reset = col u, z = col u+64
        float a1[4], a2[4];
        #pragma unroll
        for (int j = 0; j < 4; j++) { a1[j] = sb1[u]; a2[j] = sb1[64 + u]; }
        #pragma unroll 5
        for (int f = 0; f < Ff; f++) {
            float w1 = sW1[f*128 + u];
            float w2 = sW1[f*128 + 64 + u];
            #pragma unroll
            for (int j = 0; j < 4; j++) {
                float xv = sh2[(ln0 + j)*(Ff+1) + f];
                a1[j] += xv * w1;
                a2[j] += xv * w2;
            }
        }
        float rst[4], zz[4];
        #pragma unroll
        for (int j = 0; j < 4; j++) {
            rst[j] = 1.f / (1.f + __expf(-a1[j]));
            zz[j]  = 1.f / (1.f + __expf(-a2[j]));
            srh2[(ln0 + j)*(Ff+1) + 1 + u] = rst[j] * h2v[j];
            if (u == 0) srh2[(ln0 + j)*(Ff+1) + 0] = xinv[j];
        }
        __syncthreads();

        // c = tanh([xin, reset*h2] @ W2 + b2)
        float cacc[4];
        #pragma unroll
        for (int j = 0; j < 4; j++) cacc[j] = sb2[u];
        #pragma unroll 5
        for (int f = 0; f < Ff; f++) {
            float w = sW2[f*Uu + u];
            #pragma unroll
            for (int j = 0; j < 4; j++)
                cacc[j] += srh2[(ln0 + j)*(Ff+1) + f] * w;
        }
        #pragma unroll
        for (int j = 0; j < 4; j++) {
            int node = base + ln0 + j;
            if (nodeok[j]) {
                float cc = tanhf(cacc[j]);
                out[(size_t)node*Uu + u] = (1.f - zz[j]) * h2v[j] + zz[j] * cc;
            }
        }
    }
}

// ---------------- launch ----------------
extern "C" void kernel_launch(void* const* d_in, const int* in_sizes, int n_in,
                              void* d_out, int out_size)
{
    const float* inputs = (const float*)d_in[0];
    const float* state  = (const float*)d_in[1];
    const int*   esrc   = (const int*)d_in[2];
    const int*   edst   = (const int*)d_in[3];
    const float* Wq = (const float*)d_in[4];
    const float* bq = (const float*)d_in[5];
    const float* Wk = (const float*)d_in[6];
    const float* bk = (const float*)d_in[7];
    const float* Wv = (const float*)d_in[8];
    const float* bv = (const float*)d_in[9];
    const float* Ws = (const float*)d_in[10];
    const float* bs = (const float*)d_in[11];
    const float* W1 = (const float*)d_in[12];
    const float* b1 = (const float*)d_in[13];
    const float* W2 = (const float*)d_in[14];
    const float* b2 = (const float*)d_in[15];
    float* out = (float*)d_out;

    const int SMEM_A = (3*Ff*Uu + 3*Uu + 16*(Ff+1)) * (int)sizeof(float);
    const int SMEM_D = (Ff*Uu + Ff*128 + Ff*Uu + Uu + 128 + Uu + 3*16*(Ff+1)) * (int)sizeof(float);

    cudaFuncSetAttribute(qkv_kernel, cudaFuncAttributeMaxDynamicSharedMemorySize, SMEM_A);
    cudaFuncSetAttribute(gru_kernel, cudaFuncAttributeMaxDynamicSharedMemorySize, SMEM_D);

    // CSR build
    zero_cnt_kernel<<<(Nn + 255)/256, 256>>>();
    hist_kernel<<<(Ee + 255)/256, 256>>>(edst);
    scan_kernel<<<1, 1024>>>();
    scatter_kernel<<<(Ee + 255)/256, 256>>>(edst);

    // projections
    qkv_kernel<<<592, 256, SMEM_A>>>(inputs, state, Wq, bq, Wk, bk, Wv, bv);

    // attention
    attn_kernel<<<NODES, 128>>>(esrc);

    // fused GRU
    gru_kernel<<<296, 256, SMEM_D>>>(inputs, state, Ws, bs, W1, b1, W2, b2, out);
}

// round 2
// speedup vs baseline: 1.3164x; 1.3164x over previous
#include <cuda_runtime.h>
#include <cuda_fp16.h>
#include <math.h>

#define Bb 4
#define Nn 20000
#define Uu 64
#define Ff 65
#define Ee 640000
#define NODES (Bb*Nn)
#define ATT_SCALE 0.125f

// ---------------- device scratch (static, no runtime alloc) ----------------
__device__ float  g_q[NODES*Uu];
__device__ __half g_kh[NODES*Uu];
__device__ __half g_vh[NODES*Uu];
__device__ float  g_agg[NODES*Uu];
__device__ unsigned char g_mask[NODES];
__device__ int g_cnt[Nn];
__device__ int g_off[Nn];
__device__ int g_cur[Nn];
__device__ int g_srt[Ee];   // src ids sorted by dst (CSR payload)

// ---------------- CSR build ----------------
__global__ void zero_cnt_kernel() {
    int i = blockIdx.x * blockDim.x + threadIdx.x;
    if (i < Nn) g_cnt[i] = 0;
}

__global__ void hist_kernel(const int* __restrict__ edst) {
    int i = blockIdx.x * blockDim.x + threadIdx.x;
    if (i < Ee) atomicAdd(&g_cnt[edst[i]], 1);
}

__global__ void scan_kernel() {
    __shared__ int sp[1024];
    int tid = threadIdx.x;
    int base = tid * 20;
    int s = 0;
    #pragma unroll
    for (int i = 0; i < 20; i++) {
        int idx = base + i;
        if (idx < Nn) s += g_cnt[idx];
    }
    sp[tid] = s;
    __syncthreads();
    for (int d = 1; d < 1024; d <<= 1) {
        int v = (tid >= d) ? sp[tid - d] : 0;
        __syncthreads();
        sp[tid] += v;
        __syncthreads();
    }
    int run = sp[tid] - s;   // exclusive prefix
    #pragma unroll
    for (int i = 0; i < 20; i++) {
        int idx = base + i;
        if (idx < Nn) {
            g_off[idx] = run;
            g_cur[idx] = run;
            run += g_cnt[idx];
        }
    }
}

__global__ void scatter_kernel(const int* __restrict__ edst,
                               const int* __restrict__ esrc) {
    int i = blockIdx.x * blockDim.x + threadIdx.x;
    if (i < Ee) {
        int pos = atomicAdd(&g_cur[edst[i]], 1);
        g_srt[pos] = esrc[i];
    }
}

// ---------------- QKV projection + mask ----------------
__global__ void __launch_bounds__(256) qkv_kernel(
    const float* __restrict__ inputs, const float* __restrict__ state,
    const float* __restrict__ Wq, const float* __restrict__ bq,
    const float* __restrict__ Wk, const float* __restrict__ bk,
    const float* __restrict__ Wv, const float* __restrict__ bv)
{
    extern __shared__ float sm[];
    float* sWq = sm;                       // F*U
    float* sWk = sWq + Ff*Uu;              // F*U
    float* sWv = sWk + Ff*Uu;              // F*U
    float* sb  = sWv + Ff*Uu;              // 3*U
    float* sx  = sb + 3*Uu;                // 16 * 66

    for (int i = threadIdx.x; i < Ff*Uu; i += 256) {
        sWq[i] = Wq[i]; sWk[i] = Wk[i]; sWv[i] = Wv[i];
    }
    if (threadIdx.x < Uu) {
        sb[threadIdx.x]        = bq[threadIdx.x];
        sb[threadIdx.x + Uu]   = bk[threadIdx.x];
        sb[threadIdx.x + 2*Uu] = bv[threadIdx.x];
    }
    __syncthreads();

    int u = threadIdx.x & 63;
    int g = threadIdx.x >> 6;
    int ln0 = g * 4;
    int nChunks = (NODES + 15) / 16;

    for (int c = blockIdx.x; c < nChunks; c += gridDim.x) {
        int base = c * 16;
        __syncthreads();
        for (int i = threadIdx.x; i < 16*Ff; i += 256) {
            int ln = i / Ff, f = i - ln*Ff;
            int node = base + ln;
            float v = 0.f;
            if (node < NODES) {
                int b = node / Nn, n = node - b*Nn;
                v = (f < Uu) ? state[(size_t)b*Nn*Uu + (size_t)n*Uu + f]
                             : inputs[b*Nn + n];
            }
            sx[ln*(Ff+1) + f] = v;
        }
        __syncthreads();
        if (threadIdx.x < 16) {
            int node = base + threadIdx.x;
            if (node < NODES)
                g_mask[node] = (sx[threadIdx.x*(Ff+1) + 58] != 0.f) ? 1 : 0;
        }

        float aq[4] = {0,0,0,0}, ak[4] = {0,0,0,0}, av[4] = {0,0,0,0};
        #pragma unroll 5
        for (int f = 0; f < Ff; f++) {
            float wq = sWq[f*Uu + u];
            float wk = sWk[f*Uu + u];
            float wv = sWv[f*Uu + u];
            #pragma unroll
            for (int j = 0; j < 4; j++) {
                float xv = sx[(ln0 + j)*(Ff+1) + f];
                aq[j] += xv * wq;
                ak[j] += xv * wk;
                av[j] += xv * wv;
            }
        }
        #pragma unroll
        for (int j = 0; j < 4; j++) {
            int node = base + ln0 + j;
            if (node < NODES) {
                size_t idx = (size_t)node*Uu + u;
                g_q[idx]  = aq[j] + sb[u];
                g_kh[idx] = __float2half_rn(ak[j] + sb[Uu + u]);
                g_vh[idx] = __float2half_rn(av[j] + sb[2*Uu + u]);
            }
        }
    }
}

// ---------------- attention: one warp per (b, dst) ----------------
// Softmax without max-subtraction (shift-invariant, scores O(+-8)).
// Warp-local: no smem, no barriers. K/V in fp16 (halves gather traffic).
__global__ void __launch_bounds__(256) attn_kernel() {
    int gw = (blockIdx.x * blockDim.x + threadIdx.x) >> 5;
    if (gw >= NODES) return;
    if (!g_mask[gw]) return;

    int lane = threadIdx.x & 31;
    int b = gw / Nn;
    int n = gw - b * Nn;

    size_t rowbase = (size_t)gw * Uu;
    float2 q = ((const float2*)(g_q + rowbase))[lane];

    int off = g_off[n];
    int deg = g_cnt[n];
    const __half2* kb = ((const __half2*)g_kh) + (size_t)b * Nn * 32;
    const __half2* vb = ((const __half2*)g_vh) + (size_t)b * Nn * 32;
    const unsigned char* mk = g_mask + b * Nn;

    float accx = 0.f, accy = 0.f, den = 0.f;

    int t = off;
    int end = off + deg;
    for (; t + 1 < end; t += 2) {
        int s0 = __ldg(&g_srt[t]);
        int s1 = __ldg(&g_srt[t + 1]);
        float2 k0 = __half22float2(kb[(size_t)s0 * 32 + lane]);
        float2 k1 = __half22float2(kb[(size_t)s1 * 32 + lane]);
        float p0 = k0.x * q.x + k0.y * q.y;
        float p1 = k1.x * q.x + k1.y * q.y;
        #pragma unroll
        for (int d = 16; d; d >>= 1) {
            p0 += __shfl_xor_sync(0xffffffffu, p0, d);
            p1 += __shfl_xor_sync(0xffffffffu, p1, d);
        }
        float w0 = mk[s0] ? __expf(p0 * ATT_SCALE) : 0.f;
        float w1 = mk[s1] ? __expf(p1 * ATT_SCALE) : 0.f;
        float2 v0 = __half22float2(vb[(size_t)s0 * 32 + lane]);
        float2 v1 = __half22float2(vb[(size_t)s1 * 32 + lane]);
        accx += w0 * v0.x + w1 * v1.x;
        accy += w0 * v0.y + w1 * v1.y;
        den  += w0 + w1;
    }
    if (t < end) {
        int s0 = __ldg(&g_srt[t]);
        float2 k0 = __half22float2(kb[(size_t)s0 * 32 + lane]);
        float p0 = k0.x * q.x + k0.y * q.y;
        #pragma unroll
        for (int d = 16; d; d >>= 1)
            p0 += __shfl_xor_sync(0xffffffffu, p0, d);
        float w0 = mk[s0] ? __expf(p0 * ATT_SCALE) : 0.f;
        float2 v0 = __half22float2(vb[(size_t)s0 * 32 + lane]);
        accx += w0 * v0.x;
        accy += w0 * v0.y;
        den  += w0;
    }

    float inv = (den > 0.f) ? 1.f / fmaxf(den, 1e-16f) : 0.f;
    ((float2*)(g_agg + rowbase))[lane] = make_float2(accx * inv, accy * inv);
}

// ---------------- fused GRU epilogue ----------------
__global__ void __launch_bounds__(256) gru_kernel(
    const float* __restrict__ inputs, const float* __restrict__ state,
    const float* __restrict__ Ws, const float* __restrict__ bs,
    const float* __restrict__ W1, const float* __restrict__ b1,
    const float* __restrict__ W2, const float* __restrict__ b2,
    float* __restrict__ out)
{
    extern __shared__ float sm[];
    float* sWs = sm;                         // F*U
    float* sW1 = sWs + Ff*Uu;                // F*128
    float* sW2 = sW1 + Ff*128;               // F*U
    float* sbs = sW2 + Ff*Uu;                // U
    float* sb1 = sbs + Uu;                   // 128
    float* sb2 = sb1 + 128;                  // U
    float* sx   = sb2 + Uu;                  // 16*66  x = [h, xin]
    float* sh2  = sx  + 16*(Ff+1);           // 16*66  cat1 = [xin, h2]
    float* srh2 = sh2 + 16*(Ff+1);           // 16*66  [xin, reset*h2]

    for (int i = threadIdx.x; i < Ff*Uu; i += 256)  sWs[i] = Ws[i];
    for (int i = threadIdx.x; i < Ff*128; i += 256) sW1[i] = W1[i];
    for (int i = threadIdx.x; i < Ff*Uu; i += 256)  sW2[i] = W2[i];
    if (threadIdx.x < Uu)  sbs[threadIdx.x] = bs[threadIdx.x];
    if (threadIdx.x < 128) sb1[threadIdx.x] = b1[threadIdx.x];
    if (threadIdx.x < Uu)  sb2[threadIdx.x] = b2[threadIdx.x];
    __syncthreads();

    int u = threadIdx.x & 63;
    int g = threadIdx.x >> 6;
    int ln0 = g * 4;
    int nChunks = (NODES + 15) / 16;

    for (int c = blockIdx.x; c < nChunks; c += gridDim.x) {
        int base = c * 16;
        __syncthreads();
        for (int i = threadIdx.x; i < 16*Ff; i += 256) {
            int ln = i / Ff, f = i - ln*Ff;
            int node = base + ln;
            float v = 0.f;
            if (node < NODES) {
                int b = node / Nn, n = node - b*Nn;
                v = (f < Uu) ? state[(size_t)b*Nn*Uu + (size_t)n*Uu + f]
                             : inputs[b*Nn + n];
            }
            sx[ln*(Ff+1) + f] = v;
        }
        __syncthreads();

        // s = x @ Ws + bs
        float sacc[4] = {0,0,0,0};
        #pragma unroll 5
        for (int f = 0; f < Ff; f++) {
            float w = sWs[f*Uu + u];
            #pragma unroll
            for (int j = 0; j < 4; j++)
                sacc[j] += sx[(ln0 + j)*(Ff+1) + f] * w;
        }

        float h2v[4], xinv[4];
        bool nodeok[4];
        #pragma unroll
        for (int j = 0; j < 4; j++) {
            int ln = ln0 + j;
            int node = base + ln;
            nodeok[j] = (node < NODES);
            float hv  = sx[ln*(Ff+1) + u];
            xinv[j]   = sx[ln*(Ff+1) + Uu];
            bool msk  = (sx[ln*(Ff+1) + 58] != 0.f);
            float av  = nodeok[j] ? g_agg[(size_t)(nodeok[j] ? node : 0)*Uu + u] : 0.f;
            float h2  = msk ? (av + sacc[j] + sbs[u]) : hv;
            h2v[j] = h2;
            sh2[ln*(Ff+1) + 1 + u] = h2;
            if (u == 0) sh2[ln*(Ff+1) + 0] = xinv[j];
        }
        __syncthreads();

        // value = sigmoid(cat1 @ W1 + b1): reset = col u, z = col u+64
        float a1[4], a2[4];
        #pragma unroll
        for (int j = 0; j < 4; j++) { a1[j] = sb1[u]; a2[j] = sb1[64 + u]; }
        #pragma unroll 5
        for (int f = 0; f < Ff; f++) {
            float w1 = sW1[f*128 + u];
            float w2 = sW1[f*128 + 64 + u];
            #pragma unroll
            for (int j = 0; j < 4; j++) {
                float xv = sh2[(ln0 + j)*(Ff+1) + f];
                a1[j] += xv * w1;
                a2[j] += xv * w2;
            }
        }
        float zz[4];
        #pragma unroll
        for (int j = 0; j < 4; j++) {
            float rst = 1.f / (1.f + __expf(-a1[j]));
            zz[j]     = 1.f / (1.f + __expf(-a2[j]));
            srh2[(ln0 + j)*(Ff+1) + 1 + u] = rst * h2v[j];
            if (u == 0) srh2[(ln0 + j)*(Ff+1) + 0] = xinv[j];
        }
        __syncthreads();

        // c = tanh([xin, reset*h2] @ W2 + b2)
        float cacc[4];
        #pragma unroll
        for (int j = 0; j < 4; j++) cacc[j] = sb2[u];
        #pragma unroll 5
        for (int f = 0; f < Ff; f++) {
            float w = sW2[f*Uu + u];
            #pragma unroll
            for (int j = 0; j < 4; j++)
                cacc[j] += srh2[(ln0 + j)*(Ff+1) + f] * w;
        }
        #pragma unroll
        for (int j = 0; j < 4; j++) {
            int node = base + ln0 + j;
            if (nodeok[j]) {
                float cc = tanhf(cacc[j]);
                out[(size_t)node*Uu + u] = (1.f - zz[j]) * h2v[j] + zz[j] * cc;
            }
        }
    }
}

// ---------------- launch ----------------
extern "C" void kernel_launch(void* const* d_in, const int* in_sizes, int n_in,
                              void* d_out, int out_size)
{
    const float* inputs = (const float*)d_in[0];
    const float* state  = (const float*)d_in[1];
    const int*   esrc   = (const int*)d_in[2];
    const int*   edst   = (const int*)d_in[3];
    const float* Wq = (const float*)d_in[4];
    const float* bq = (const float*)d_in[5];
    const float* Wk = (const float*)d_in[6];
    const float* bk = (const float*)d_in[7];
    const float* Wv = (const float*)d_in[8];
    const float* bv = (const float*)d_in[9];
    const float* Ws = (const float*)d_in[10];
    const float* bs = (const float*)d_in[11];
    const float* W1 = (const float*)d_in[12];
    const float* b1 = (const float*)d_in[13];
    const float* W2 = (const float*)d_in[14];
    const float* b2 = (const float*)d_in[15];
    float* out = (float*)d_out;

    const int SMEM_A = (3*Ff*Uu + 3*Uu + 16*(Ff+1)) * (int)sizeof(float);
    const int SMEM_D = (Ff*Uu + Ff*128 + Ff*Uu + Uu + 128 + Uu + 3*16*(Ff+1)) * (int)sizeof(float);

    cudaFuncSetAttribute(qkv_kernel, cudaFuncAttributeMaxDynamicSharedMemorySize, SMEM_A);
    cudaFuncSetAttribute(gru_kernel, cudaFuncAttributeMaxDynamicSharedMemorySize, SMEM_D);

    // CSR build
    zero_cnt_kernel<<<(Nn + 255)/256, 256>>>();
    hist_kernel<<<(Ee + 255)/256, 256>>>(edst);
    scan_kernel<<<1, 1024>>>();
    scatter_kernel<<<(Ee + 255)/256, 256>>>(edst, esrc);

    // projections
    qkv_kernel<<<592, 256, SMEM_A>>>(inputs, state, Wq, bq, Wk, bk, Wv, bv);

    // attention: one warp per (b, dst)
    attn_kernel<<<(NODES*32 + 255)/256, 256>>>();

    // fused GRU
    gru_kernel<<<296, 256, SMEM_D>>>(inputs, state, Ws, bs, W1, b1, W2, b2, out);
}

// round 3
// speedup vs baseline: 1.4857x; 1.1286x over previous
#include <cuda_runtime.h>
#include <cuda_fp16.h>
#include <math.h>

#define Bb 4
#define Nn 20000
#define Uu 64
#define Ff 65
#define Ee 640000
#define NODES (Bb*Nn)
#define ATT_SCALE 0.125f

// ---------------- device scratch (static, no runtime alloc) ----------------
__device__ __align__(16) __half g_qh[NODES*Uu];   // prescaled by ATT_SCALE
__device__ __align__(16) __half g_kh[NODES*Uu];
__device__ __align__(16) __half g_vh[NODES*Uu];
__device__ __align__(16) float  g_agg[NODES*Uu];
__device__ unsigned char g_mask[NODES];
__device__ int g_cnt[Nn];
__device__ int g_off[Nn];
__device__ int g_cur[Nn];
__device__ int g_srt[Ee];   // src ids sorted by dst (CSR payload)

// ---------------- CSR build ----------------
__global__ void zero_cnt_kernel() {
    int i = blockIdx.x * blockDim.x + threadIdx.x;
    if (i < Nn) g_cnt[i] = 0;
}

__global__ void hist_kernel(const int* __restrict__ edst) {
    int i = blockIdx.x * blockDim.x + threadIdx.x;
    if (i < Ee) atomicAdd(&g_cnt[edst[i]], 1);
}

__global__ void scan_kernel() {
    __shared__ int sp[1024];
    int tid = threadIdx.x;
    int base = tid * 20;
    int s = 0;
    #pragma unroll
    for (int i = 0; i < 20; i++) {
        int idx = base + i;
        if (idx < Nn) s += g_cnt[idx];
    }
    sp[tid] = s;
    __syncthreads();
    for (int d = 1; d < 1024; d <<= 1) {
        int v = (tid >= d) ? sp[tid - d] : 0;
        __syncthreads();
        sp[tid] += v;
        __syncthreads();
    }
    int run = sp[tid] - s;   // exclusive prefix
    #pragma unroll
    for (int i = 0; i < 20; i++) {
        int idx = base + i;
        if (idx < Nn) {
            g_off[idx] = run;
            g_cur[idx] = run;
            run += g_cnt[idx];
        }
    }
}

__global__ void scatter_kernel(const int* __restrict__ edst,
                               const int* __restrict__ esrc) {
    int i = blockIdx.x * blockDim.x + threadIdx.x;
    if (i < Ee) {
        int pos = atomicAdd(&g_cur[edst[i]], 1);
        g_srt[pos] = esrc[i];
    }
}

// ---------------- QKV projection + mask ----------------
__global__ void __launch_bounds__(256) qkv_kernel(
    const float* __restrict__ inputs, const float* __restrict__ state,
    const float* __restrict__ Wq, const float* __restrict__ bq,
    const float* __restrict__ Wk, const float* __restrict__ bk,
    const float* __restrict__ Wv, const float* __restrict__ bv)
{
    extern __shared__ float sm[];
    float* sWq = sm;                       // F*U
    float* sWk = sWq + Ff*Uu;              // F*U
    float* sWv = sWk + Ff*Uu;              // F*U
    float* sb  = sWv + Ff*Uu;              // 3*U
    float* sx  = sb + 3*Uu;                // 16 * 66

    for (int i = threadIdx.x; i < Ff*Uu; i += 256) {
        sWq[i] = Wq[i]; sWk[i] = Wk[i]; sWv[i] = Wv[i];
    }
    if (threadIdx.x < Uu) {
        sb[threadIdx.x]        = bq[threadIdx.x];
        sb[threadIdx.x + Uu]   = bk[threadIdx.x];
        sb[threadIdx.x + 2*Uu] = bv[threadIdx.x];
    }
    __syncthreads();

    int u = threadIdx.x & 63;
    int g = threadIdx.x >> 6;
    int ln0 = g * 4;
    int nChunks = (NODES + 15) / 16;

    for (int c = blockIdx.x; c < nChunks; c += gridDim.x) {
        int base = c * 16;
        __syncthreads();
        for (int i = threadIdx.x; i < 16*Ff; i += 256) {
            int ln = i / Ff, f = i - ln*Ff;
            int node = base + ln;
            float v = 0.f;
            if (node < NODES) {
                int b = node / Nn, n = node - b*Nn;
                v = (f < Uu) ? state[(size_t)b*Nn*Uu + (size_t)n*Uu + f]
                             : inputs[b*Nn + n];
            }
            sx[ln*(Ff+1) + f] = v;
        }
        __syncthreads();
        if (threadIdx.x < 16) {
            int node = base + threadIdx.x;
            if (node < NODES)
                g_mask[node] = (sx[threadIdx.x*(Ff+1) + 58] != 0.f) ? 1 : 0;
        }

        float aq[4] = {0,0,0,0}, ak[4] = {0,0,0,0}, av[4] = {0,0,0,0};
        #pragma unroll 5
        for (int f = 0; f < Ff; f++) {
            float wq = sWq[f*Uu + u];
            float wk = sWk[f*Uu + u];
            float wv = sWv[f*Uu + u];
            #pragma unroll
            for (int j = 0; j < 4; j++) {
                float xv = sx[(ln0 + j)*(Ff+1) + f];
                aq[j] += xv * wq;
                ak[j] += xv * wk;
                av[j] += xv * wv;
            }
        }
        #pragma unroll
        for (int j = 0; j < 4; j++) {
            int node = base + ln0 + j;
            if (node < NODES) {
                size_t idx = (size_t)node*Uu + u;
                g_qh[idx] = __float2half_rn((aq[j] + sb[u]) * ATT_SCALE);
                g_kh[idx] = __float2half_rn(ak[j] + sb[Uu + u]);
                g_vh[idx] = __float2half_rn(av[j] + sb[2*Uu + u]);
            }
        }
    }
}

// ---------------- attention: one warp per (b, dst), 8 lanes per edge -------
// 4 edges processed per warp step; butterfly reduce (3 shfls) shared by all
// 4 edges. Softmax without max-subtraction (shift-invariant, scores O(+-8)).
__device__ __forceinline__ void ld_h8(const __half* p, float2 f[4]) {
    uint4 r = *reinterpret_cast<const uint4*>(p);
    f[0] = __half22float2(*reinterpret_cast<__half2*>(&r.x));
    f[1] = __half22float2(*reinterpret_cast<__half2*>(&r.y));
    f[2] = __half22float2(*reinterpret_cast<__half2*>(&r.z));
    f[3] = __half22float2(*reinterpret_cast<__half2*>(&r.w));
}

__global__ void __launch_bounds__(256) attn_kernel() {
    int gw = (blockIdx.x * blockDim.x + threadIdx.x) >> 5;
    if (gw >= NODES) return;
    if (!g_mask[gw]) return;

    int lane = threadIdx.x & 31;
    int grp  = lane >> 3;     // edge slot 0..3
    int sub  = lane & 7;      // dim group: dims [sub*8, sub*8+8)
    int b = gw / Nn;
    int n = gw - b * Nn;

    size_t rowbase = (size_t)gw * Uu;
    float2 q[4];
    ld_h8(g_qh + rowbase + sub*8, q);

    int off = g_off[n];
    int deg = g_cnt[n];
    int end = off + deg;
    const __half* kb = g_kh + (size_t)b * Nn * Uu;
    const __half* vb = g_vh + (size_t)b * Nn * Uu;
    const unsigned char* mk = g_mask + b * Nn;

    float2 acc[4] = {{0,0},{0,0},{0,0},{0,0}};
    float den = 0.f;

    for (int t = off; t < end; t += 8) {
        int e0 = t + grp;
        int e1 = t + 4 + grp;
        bool val0 = e0 < end;
        bool val1 = e1 < end;
        int s0 = __ldg(&g_srt[val0 ? e0 : off]);
        int s1 = __ldg(&g_srt[val1 ? e1 : off]);

        float2 k0[4], k1[4];
        ld_h8(kb + (size_t)s0 * Uu + sub*8, k0);
        ld_h8(kb + (size_t)s1 * Uu + sub*8, k1);

        float p0 = k0[0].x*q[0].x + k0[0].y*q[0].y
                 + k0[1].x*q[1].x + k0[1].y*q[1].y
                 + k0[2].x*q[2].x + k0[2].y*q[2].y
                 + k0[3].x*q[3].x + k0[3].y*q[3].y;
        float p1 = k1[0].x*q[0].x + k1[0].y*q[0].y
                 + k1[1].x*q[1].x + k1[1].y*q[1].y
                 + k1[2].x*q[2].x + k1[2].y*q[2].y
                 + k1[3].x*q[3].x + k1[3].y*q[3].y;
        #pragma unroll
        for (int d = 1; d < 8; d <<= 1) {
            p0 += __shfl_xor_sync(0xffffffffu, p0, d);
            p1 += __shfl_xor_sync(0xffffffffu, p1, d);
        }
        float w0 = (val0 && mk[s0]) ? __expf(p0) : 0.f;
        float w1 = (val1 && mk[s1]) ? __expf(p1) : 0.f;

        float2 v0[4], v1[4];
        ld_h8(vb + (size_t)s0 * Uu + sub*8, v0);
        ld_h8(vb + (size_t)s1 * Uu + sub*8, v1);
        #pragma unroll
        for (int i = 0; i < 4; i++) {
            acc[i].x += w0 * v0[i].x + w1 * v1[i].x;
            acc[i].y += w0 * v0[i].y + w1 * v1[i].y;
        }
        den += w0 + w1;
    }

    // cross-group reduce (groups 0..3 hold disjoint edge subsets)
    #pragma unroll
    for (int d = 8; d < 32; d <<= 1) {
        #pragma unroll
        for (int i = 0; i < 4; i++) {
            acc[i].x += __shfl_xor_sync(0xffffffffu, acc[i].x, d);
            acc[i].y += __shfl_xor_sync(0xffffffffu, acc[i].y, d);
        }
        den += __shfl_xor_sync(0xffffffffu, den, d);
    }

    if (lane < 8) {
        float inv = (den > 0.f) ? 1.f / fmaxf(den, 1e-16f) : 0.f;
        float4* op = (float4*)(g_agg + rowbase + sub * 8);
        op[0] = make_float4(acc[0].x*inv, acc[0].y*inv, acc[1].x*inv, acc[1].y*inv);
        op[1] = make_float4(acc[2].x*inv, acc[2].y*inv, acc[3].x*inv, acc[3].y*inv);
    }
}

// ---------------- fused GRU epilogue ----------------
__global__ void __launch_bounds__(256) gru_kernel(
    const float* __restrict__ inputs, const float* __restrict__ state,
    const float* __restrict__ Ws, const float* __restrict__ bs,
    const float* __restrict__ W1, const float* __restrict__ b1,
    const float* __restrict__ W2, const float* __restrict__ b2,
    float* __restrict__ out)
{
    extern __shared__ float sm[];
    float* sWs = sm;                         // F*U
    float* sW1 = sWs + Ff*Uu;                // F*128
    float* sW2 = sW1 + Ff*128;               // F*U
    float* sbs = sW2 + Ff*Uu;                // U
    float* sb1 = sbs + Uu;                   // 128
    float* sb2 = sb1 + 128;                  // U
    float* sx   = sb2 + Uu;                  // 16*66  x = [h, xin]
    float* sh2  = sx  + 16*(Ff+1);           // 16*66  cat1 = [xin, h2]
    float* srh2 = sh2 + 16*(Ff+1);           // 16*66  [xin, reset*h2]

    for (int i = threadIdx.x; i < Ff*Uu; i += 256)  sWs[i] = Ws[i];
    for (int i = threadIdx.x; i < Ff*128; i += 256) sW1[i] = W1[i];
    for (int i = threadIdx.x; i < Ff*Uu; i += 256)  sW2[i] = W2[i];
    if (threadIdx.x < Uu)  sbs[threadIdx.x] = bs[threadIdx.x];
    if (threadIdx.x < 128) sb1[threadIdx.x] = b1[threadIdx.x];
    if (threadIdx.x < Uu)  sb2[threadIdx.x] = b2[threadIdx.x];
    __syncthreads();

    int u = threadIdx.x & 63;
    int g = threadIdx.x >> 6;
    int ln0 = g * 4;
    int nChunks = (NODES + 15) / 16;

    for (int c = blockIdx.x; c < nChunks; c += gridDim.x) {
        int base = c * 16;
        __syncthreads();
        for (int i = threadIdx.x; i < 16*Ff; i += 256) {
            int ln = i / Ff, f = i - ln*Ff;
            int node = base + ln;
            float v = 0.f;
            if (node < NODES) {
                int b = node / Nn, n = node - b*Nn;
                v = (f < Uu) ? state[(size_t)b*Nn*Uu + (size_t)n*Uu + f]
                             : inputs[b*Nn + n];
            }
            sx[ln*(Ff+1) + f] = v;
        }
        __syncthreads();

        // s = x @ Ws + bs
        float sacc[4] = {0,0,0,0};
        #pragma unroll 5
        for (int f = 0; f < Ff; f++) {
            float w = sWs[f*Uu + u];
            #pragma unroll
            for (int j = 0; j < 4; j++)
                sacc[j] += sx[(ln0 + j)*(Ff+1) + f] * w;
        }

        float h2v[4], xinv[4];
        bool nodeok[4];
        #pragma unroll
        for (int j = 0; j < 4; j++) {
            int ln = ln0 + j;
            int node = base + ln;
            nodeok[j] = (node < NODES);
            float hv  = sx[ln*(Ff+1) + u];
            xinv[j]   = sx[ln*(Ff+1) + Uu];
            bool msk  = (sx[ln*(Ff+1) + 58] != 0.f);
            float av  = nodeok[j] ? g_agg[(size_t)(nodeok[j] ? node : 0)*Uu + u] : 0.f;
            float h2  = msk ? (av + sacc[j] + sbs[u]) : hv;
            h2v[j] = h2;
            sh2[ln*(Ff+1) + 1 + u] = h2;
            if (u == 0) sh2[ln*(Ff+1) + 0] = xinv[j];
        }
        __syncthreads();

        // value = sigmoid(cat1 @ W1 + b1): reset = col u, z = col u+64
        float a1[4], a2[4];
        #pragma unroll
        for (int j = 0; j < 4; j++) { a1[j] = sb1[u]; a2[j] = sb1[64 + u]; }
        #pragma unroll 5
        for (int f = 0; f < Ff; f++) {
            float w1 = sW1[f*128 + u];
            float w2 = sW1[f*128 + 64 + u];
            #pragma unroll
            for (int j = 0; j < 4; j++) {
                float xv = sh2[(ln0 + j)*(Ff+1) + f];
                a1[j] += xv * w1;
                a2[j] += xv * w2;
            }
        }
        float zz[4];
        #pragma unroll
        for (int j = 0; j < 4; j++) {
            float rst = 1.f / (1.f + __expf(-a1[j]));
            zz[j]     = 1.f / (1.f + __expf(-a2[j]));
            srh2[(ln0 + j)*(Ff+1) + 1 + u] = rst * h2v[j];
            if (u == 0) srh2[(ln0 + j)*(Ff+1) + 0] = xinv[j];
        }
        __syncthreads();

        // c = tanh([xin, reset*h2] @ W2 + b2)
        float cacc[4];
        #pragma unroll
        for (int j = 0; j < 4; j++) cacc[j] = sb2[u];
        #pragma unroll 5
        for (int f = 0; f < Ff; f++) {
            float w = sW2[f*Uu + u];
            #pragma unroll
            for (int j = 0; j < 4; j++)
                cacc[j] += srh2[(ln0 + j)*(Ff+1) + f] * w;
        }
        #pragma unroll
        for (int j = 0; j < 4; j++) {
            int node = base + ln0 + j;
            if (nodeok[j]) {
                float cc = tanhf(cacc[j]);
                out[(size_t)node*Uu + u] = (1.f - zz[j]) * h2v[j] + zz[j] * cc;
            }
        }
    }
}

// ---------------- launch ----------------
extern "C" void kernel_launch(void* const* d_in, const int* in_sizes, int n_in,
                              void* d_out, int out_size)
{
    const float* inputs = (const float*)d_in[0];
    const float* state  = (const float*)d_in[1];
    const int*   esrc   = (const int*)d_in[2];
    const int*   edst   = (const int*)d_in[3];
    const float* Wq = (const float*)d_in[4];
    const float* bq = (const float*)d_in[5];
    const float* Wk = (const float*)d_in[6];
    const float* bk = (const float*)d_in[7];
    const float* Wv = (const float*)d_in[8];
    const float* bv = (const float*)d_in[9];
    const float* Ws = (const float*)d_in[10];
    const float* bs = (const float*)d_in[11];
    const float* W1 = (const float*)d_in[12];
    const float* b1 = (const float*)d_in[13];
    const float* W2 = (const float*)d_in[14];
    const float* b2 = (const float*)d_in[15];
    float* out = (float*)d_out;

    const int SMEM_A = (3*Ff*Uu + 3*Uu + 16*(Ff+1)) * (int)sizeof(float);
    const int SMEM_D = (Ff*Uu + Ff*128 + Ff*Uu + Uu + 128 + Uu + 3*16*(Ff+1)) * (int)sizeof(float);

    cudaFuncSetAttribute(qkv_kernel, cudaFuncAttributeMaxDynamicSharedMemorySize, SMEM_A);
    cudaFuncSetAttribute(gru_kernel, cudaFuncAttributeMaxDynamicSharedMemorySize, SMEM_D);

    // CSR build
    zero_cnt_kernel<<<(Nn + 255)/256, 256>>>();
    hist_kernel<<<(Ee + 255)/256, 256>>>(edst);
    scan_kernel<<<1, 1024>>>();
    scatter_kernel<<<(Ee + 255)/256, 256>>>(edst, esrc);

    // projections
    qkv_kernel<<<592, 256, SMEM_A>>>(inputs, state, Wq, bq, Wk, bk, Wv, bv);

    // attention: one warp per (b, dst), 8 lanes per edge
    attn_kernel<<<(NODES*32 + 255)/256, 256>>>();

    // fused GRU
    gru_kernel<<<296, 256, SMEM_D>>>(inputs, state, Ws, bs, W1, b1, W2, b2, out);
}

// round 4
// speedup vs baseline: 1.9269x; 1.2970x over previous
#include <cuda_runtime.h>
#include <cuda_fp16.h>
#include <math.h>

#define Bb 4
#define Nn 20000
#define Uu 64
#define Ff 65
#define Ee 640000
#define NODES (Bb*Nn)
#define ATT_SCALE 0.125f
#define FP 68          // padded feature stride (68 % 8 == 4 -> conflict-free LDS.128)

// ---------------- device scratch (static, no runtime alloc) ----------------
__device__ __align__(16) __half g_qh[NODES*Uu];   // prescaled by ATT_SCALE
__device__ __align__(16) __half g_kh[NODES*Uu];
__device__ __align__(16) __half g_vh[NODES*Uu];
__device__ __align__(16) float  g_agg[NODES*Uu];
__device__ unsigned char g_mask[NODES];
__device__ int g_cnt[Nn];
__device__ int g_off[Nn];
__device__ int g_cur[Nn];
__device__ int g_srt[Ee];   // src ids sorted by dst (CSR payload)

// ---------------- CSR build ----------------
__global__ void zero_cnt_kernel() {
    int i = blockIdx.x * blockDim.x + threadIdx.x;
    if (i < Nn) g_cnt[i] = 0;
}

__global__ void hist_kernel(const int* __restrict__ edst) {
    int i = blockIdx.x * blockDim.x + threadIdx.x;
    if (i < Ee/4) {
        int4 d = ((const int4*)edst)[i];
        atomicAdd(&g_cnt[d.x], 1);
        atomicAdd(&g_cnt[d.y], 1);
        atomicAdd(&g_cnt[d.z], 1);
        atomicAdd(&g_cnt[d.w], 1);
    }
}

__global__ void scan_kernel() {
    __shared__ int sp[1024];
    int tid = threadIdx.x;
    int base = tid * 20;
    int s = 0;
    #pragma unroll
    for (int i = 0; i < 20; i++) {
        int idx = base + i;
        if (idx < Nn) s += g_cnt[idx];
    }
    sp[tid] = s;
    __syncthreads();
    for (int d = 1; d < 1024; d <<= 1) {
        int v = (tid >= d) ? sp[tid - d] : 0;
        __syncthreads();
        sp[tid] += v;
        __syncthreads();
    }
    int run = sp[tid] - s;   // exclusive prefix
    #pragma unroll
    for (int i = 0; i < 20; i++) {
        int idx = base + i;
        if (idx < Nn) {
            g_off[idx] = run;
            g_cur[idx] = run;
            run += g_cnt[idx];
        }
    }
}

__global__ void scatter_kernel(const int* __restrict__ edst,
                               const int* __restrict__ esrc) {
    int i = blockIdx.x * blockDim.x + threadIdx.x;
    if (i < Ee/4) {
        int4 d = ((const int4*)edst)[i];
        int4 s = ((const int4*)esrc)[i];
        int p0 = atomicAdd(&g_cur[d.x], 1); g_srt[p0] = s.x;
        int p1 = atomicAdd(&g_cur[d.y], 1); g_srt[p1] = s.y;
        int p2 = atomicAdd(&g_cur[d.z], 1); g_srt[p2] = s.z;
        int p3 = atomicAdd(&g_cur[d.w], 1); g_srt[p3] = s.w;
    }
}

// ---------------- QKV projection + mask ----------------
// Transposed weights in smem (W[u][f], f padded to 68), float4 over f for both
// weights and x. 8-node register blocking; 32-node chunks (2500 exact chunks).
__global__ void __launch_bounds__(256) qkv_kernel(
    const float* __restrict__ inputs, const float* __restrict__ state,
    const float* __restrict__ Wq, const float* __restrict__ bq,
    const float* __restrict__ Wk, const float* __restrict__ bk,
    const float* __restrict__ Wv, const float* __restrict__ bv)
{
    extern __shared__ float sm[];
    float* sWqT = sm;                  // 64*FP
    float* sWkT = sWqT + 64*FP;
    float* sWvT = sWkT + 64*FP;
    float* sb   = sWvT + 64*FP;        // 192
    float* sx   = sb + 192;            // 32*FP

    for (int i = threadIdx.x; i < Ff*Uu; i += 256) {
        int f = i >> 6, u = i & 63;
        sWqT[u*FP + f] = Wq[i];
        sWkT[u*FP + f] = Wk[i];
        sWvT[u*FP + f] = Wv[i];
    }
    for (int i = threadIdx.x; i < 192; i += 256) {
        int u = i & 63, p = i >> 6;    // pad f=65..67
        sWqT[u*FP + 65 + p] = 0.f;
        sWkT[u*FP + 65 + p] = 0.f;
        sWvT[u*FP + 65 + p] = 0.f;
    }
    if (threadIdx.x < 192) sb[threadIdx.x] =
        (threadIdx.x < 64) ? bq[threadIdx.x] :
        (threadIdx.x < 128) ? bk[threadIdx.x - 64] : bv[threadIdx.x - 128];
    __syncthreads();

    int u = threadIdx.x & 63;
    int g = threadIdx.x >> 6;
    int ln0 = g * 8;
    const float4* wq4 = (const float4*)(sWqT + u*FP);
    const float4* wk4 = (const float4*)(sWkT + u*FP);
    const float4* wv4 = (const float4*)(sWvT + u*FP);

    for (int c = blockIdx.x; c < NODES/32; c += gridDim.x) {
        int base = c * 32;
        __syncthreads();
        // stage: 32 rows x 16 float4 from state (node-contiguous)
        #pragma unroll
        for (int i = threadIdx.x; i < 512; i += 256) {
            int ln = i >> 4, f4 = i & 15;
            *(float4*)(sx + ln*FP + f4*4) =
                ((const float4*)state)[(size_t)(base + ln)*16 + f4];
        }
        if (threadIdx.x < 32) {
            int node = base + threadIdx.x;
            float* row = sx + threadIdx.x*FP;
            row[64] = inputs[node];
            row[65] = 0.f; row[66] = 0.f; row[67] = 0.f;
            g_mask[node] = (__ldg(&state[(size_t)node*Uu + 58]) != 0.f) ? 1 : 0;
        }
        __syncthreads();

        float aq[8], ak[8], av[8];
        #pragma unroll
        for (int j = 0; j < 8; j++) { aq[j]=0.f; ak[j]=0.f; av[j]=0.f; }

        #pragma unroll 4
        for (int f4 = 0; f4 < 17; f4++) {
            float4 wq = wq4[f4], wk = wk4[f4], wv = wv4[f4];
            #pragma unroll
            for (int j = 0; j < 8; j++) {
                float4 xv = *(const float4*)(sx + (ln0 + j)*FP + f4*4);
                aq[j] += xv.x*wq.x + xv.y*wq.y + xv.z*wq.z + xv.w*wq.w;
                ak[j] += xv.x*wk.x + xv.y*wk.y + xv.z*wk.z + xv.w*wk.w;
                av[j] += xv.x*wv.x + xv.y*wv.y + xv.z*wv.z + xv.w*wv.w;
            }
        }
        #pragma unroll
        for (int j = 0; j < 8; j++) {
            size_t idx = (size_t)(base + ln0 + j)*Uu + u;
            g_qh[idx] = __float2half_rn((aq[j] + sb[u]) * ATT_SCALE);
            g_kh[idx] = __float2half_rn(ak[j] + sb[64 + u]);
            g_vh[idx] = __float2half_rn(av[j] + sb[128 + u]);
        }
    }
}

// ---------------- attention: one warp per (b, dst), 8 lanes per edge -------
__device__ __forceinline__ void ld_h8(const __half* p, float2 f[4]) {
    uint4 r = *reinterpret_cast<const uint4*>(p);
    f[0] = __half22float2(*reinterpret_cast<__half2*>(&r.x));
    f[1] = __half22float2(*reinterpret_cast<__half2*>(&r.y));
    f[2] = __half22float2(*reinterpret_cast<__half2*>(&r.z));
    f[3] = __half22float2(*reinterpret_cast<__half2*>(&r.w));
}

__global__ void __launch_bounds__(256) attn_kernel() {
    int gw = (blockIdx.x * blockDim.x + threadIdx.x) >> 5;
    if (gw >= NODES) return;
    if (!g_mask[gw]) return;

    int lane = threadIdx.x & 31;
    int grp  = lane >> 3;     // edge slot 0..3
    int sub  = lane & 7;      // dim group: dims [sub*8, sub*8+8)
    int b = gw / Nn;
    int n = gw - b * Nn;

    size_t rowbase = (size_t)gw * Uu;
    float2 q[4];
    ld_h8(g_qh + rowbase + sub*8, q);

    int off = g_off[n];
    int deg = g_cnt[n];
    int end = off + deg;
    const __half* kb = g_kh + (size_t)b * Nn * Uu;
    const __half* vb = g_vh + (size_t)b * Nn * Uu;
    const unsigned char* mk = g_mask + b * Nn;

    float2 acc[4] = {{0,0},{0,0},{0,0},{0,0}};
    float den = 0.f;

    // prefetch first src ids
    int sA = 0, sB = 0; bool vA = false, vB = false;
    if (off < end) {
        int eA = off + grp, eB = off + 4 + grp;
        vA = eA < end; vB = eB < end;
        sA = __ldg(&g_srt[vA ? eA : off]);
        sB = __ldg(&g_srt[vB ? eB : off]);
    }

    for (int t = off; t < end; t += 8) {
        int s0 = sA, s1 = sB;
        bool val0 = vA, val1 = vB;
        int tn = t + 8;
        if (tn < end) {          // prefetch next iteration's src ids
            int eA = tn + grp, eB = tn + 4 + grp;
            vA = eA < end; vB = eB < end;
            sA = __ldg(&g_srt[vA ? eA : off]);
            sB = __ldg(&g_srt[vB ? eB : off]);
        }

        // issue all loads up-front (mask, k, v) -> MLP ~6
        unsigned m0 = mk[s0], m1 = mk[s1];
        float2 k0[4], k1[4], v0[4], v1[4];
        ld_h8(kb + (size_t)s0 * Uu + sub*8, k0);
        ld_h8(kb + (size_t)s1 * Uu + sub*8, k1);
        ld_h8(vb + (size_t)s0 * Uu + sub*8, v0);
        ld_h8(vb + (size_t)s1 * Uu + sub*8, v1);

        float p0 = k0[0].x*q[0].x + k0[0].y*q[0].y
                 + k0[1].x*q[1].x + k0[1].y*q[1].y
                 + k0[2].x*q[2].x + k0[2].y*q[2].y
                 + k0[3].x*q[3].x + k0[3].y*q[3].y;
        float p1 = k1[0].x*q[0].x + k1[0].y*q[0].y
                 + k1[1].x*q[1].x + k1[1].y*q[1].y
                 + k1[2].x*q[2].x + k1[2].y*q[2].y
                 + k1[3].x*q[3].x + k1[3].y*q[3].y;
        #pragma unroll
        for (int d = 1; d < 8; d <<= 1) {
            p0 += __shfl_xor_sync(0xffffffffu, p0, d);
            p1 += __shfl_xor_sync(0xffffffffu, p1, d);
        }
        float w0 = (val0 && m0) ? __expf(p0) : 0.f;
        float w1 = (val1 && m1) ? __expf(p1) : 0.f;

        #pragma unroll
        for (int i = 0; i < 4; i++) {
            acc[i].x += w0 * v0[i].x + w1 * v1[i].x;
            acc[i].y += w0 * v0[i].y + w1 * v1[i].y;
        }
        den += w0 + w1;
    }

    // cross-group reduce (groups 0..3 hold disjoint edge subsets)
    #pragma unroll
    for (int d = 8; d < 32; d <<= 1) {
        #pragma unroll
        for (int i = 0; i < 4; i++) {
            acc[i].x += __shfl_xor_sync(0xffffffffu, acc[i].x, d);
            acc[i].y += __shfl_xor_sync(0xffffffffu, acc[i].y, d);
        }
        den += __shfl_xor_sync(0xffffffffu, den, d);
    }

    if (lane < 8) {
        float inv = (den > 0.f) ? 1.f / fmaxf(den, 1e-16f) : 0.f;
        float4* op = (float4*)(g_agg + rowbase + sub * 8);
        op[0] = make_float4(acc[0].x*inv, acc[0].y*inv, acc[1].x*inv, acc[1].y*inv);
        op[1] = make_float4(acc[2].x*inv, acc[2].y*inv, acc[3].x*inv, acc[3].y*inv);
    }
}

// ---------------- fused GRU epilogue ----------------
__global__ void __launch_bounds__(256) gru_kernel(
    const float* __restrict__ inputs, const float* __restrict__ state,
    const float* __restrict__ Ws, const float* __restrict__ bs,
    const float* __restrict__ W1, const float* __restrict__ b1,
    const float* __restrict__ W2, const float* __restrict__ b2,
    float* __restrict__ out)
{
    extern __shared__ float sm[];
    float* sWsT  = sm;                   // 64*FP
    float* sW1aT = sWsT  + 64*FP;        // cols 0..63
    float* sW1bT = sW1aT + 64*FP;        // cols 64..127
    float* sW2T  = sW1bT + 64*FP;
    float* sbs = sW2T + 64*FP;           // 64
    float* sb1 = sbs + 64;               // 128
    float* sb2 = sb1 + 128;              // 64
    float* sx   = sb2 + 64;              // 32*FP  x = [h, xin]
    float* sh2  = sx  + 32*FP;           // 32*FP  cat1 = [xin, h2]
    float* srh2 = sh2 + 32*FP;           // 32*FP  [xin, reset*h2]

    for (int i = threadIdx.x; i < Ff*Uu; i += 256) {
        int f = i >> 6, u = i & 63;
        sWsT[u*FP + f] = Ws[i];
        sW2T[u*FP + f] = W2[i];
    }
    for (int i = threadIdx.x; i < Ff*128; i += 256) {
        int f = i >> 7, c = i & 127;
        if (c < 64) sW1aT[c*FP + f] = W1[i];
        else        sW1bT[(c-64)*FP + f] = W1[i];
    }
    for (int i = threadIdx.x; i < 192; i += 256) {
        int u = i & 63, p = i >> 6;
        sWsT[u*FP + 65 + p] = 0.f;
        sW1aT[u*FP + 65 + p] = 0.f;
        sW1bT[u*FP + 65 + p] = 0.f;
        sW2T[u*FP + 65 + p] = 0.f;
    }
    if (threadIdx.x < 64)  sbs[threadIdx.x] = bs[threadIdx.x];
    if (threadIdx.x < 128) sb1[threadIdx.x] = b1[threadIdx.x];
    if (threadIdx.x < 64)  sb2[threadIdx.x] = b2[threadIdx.x];
    __syncthreads();

    int u = threadIdx.x & 63;
    int g = threadIdx.x >> 6;
    int ln0 = g * 8;
    const float4* ws4  = (const float4*)(sWsT  + u*FP);
    const float4* w1a4 = (const float4*)(sW1aT + u*FP);
    const float4* w1b4 = (const float4*)(sW1bT + u*FP);
    const float4* w24  = (const float4*)(sW2T  + u*FP);

    for (int c = blockIdx.x; c < NODES/32; c += gridDim.x) {
        int base = c * 32;
        __syncthreads();
        #pragma unroll
        for (int i = threadIdx.x; i < 512; i += 256) {
            int ln = i >> 4, f4 = i & 15;
            *(float4*)(sx + ln*FP + f4*4) =
                ((const float4*)state)[(size_t)(base + ln)*16 + f4];
        }
        if (threadIdx.x < 32) {
            float* row = sx + threadIdx.x*FP;
            row[64] = inputs[base + threadIdx.x];
            row[65] = 0.f; row[66] = 0.f; row[67] = 0.f;
        }
        __syncthreads();

        // phase 1: s = x @ Ws
        float acc[8];
        #pragma unroll
        for (int j = 0; j < 8; j++) acc[j] = 0.f;
        #pragma unroll 4
        for (int f4 = 0; f4 < 17; f4++) {
            float4 w = ws4[f4];
            #pragma unroll
            for (int j = 0; j < 8; j++) {
                float4 xv = *(const float4*)(sx + (ln0 + j)*FP + f4*4);
                acc[j] += xv.x*w.x + xv.y*w.y + xv.z*w.z + xv.w*w.w;
            }
        }

        float h2v[8], xinv[8];
        #pragma unroll
        for (int j = 0; j < 8; j++) {
            int ln = ln0 + j;
            int node = base + ln;
            float hv  = sx[ln*FP + u];
            xinv[j]   = sx[ln*FP + 64];
            bool msk  = (sx[ln*FP + 58] != 0.f);
            float av  = g_agg[(size_t)node*Uu + u];
            float h2  = msk ? (av + acc[j] + sbs[u]) : hv;
            h2v[j] = h2;
            sh2[ln*FP + 1 + u] = h2;
            if (u == 0) {
                sh2[ln*FP] = xinv[j];
                sh2[ln*FP + 65] = 0.f; sh2[ln*FP + 66] = 0.f; sh2[ln*FP + 67] = 0.f;
            }
        }
        __syncthreads();

        // phase 2: value = sigmoid(cat1 @ W1 + b1)
        float a1[8], a2[8];
        #pragma unroll
        for (int j = 0; j < 8; j++) { a1[j] = sb1[u]; a2[j] = sb1[64 + u]; }
        #pragma unroll 4
        for (int f4 = 0; f4 < 17; f4++) {
            float4 w1 = w1a4[f4], w2 = w1b4[f4];
            #pragma unroll
            for (int j = 0; j < 8; j++) {
                float4 xv = *(const float4*)(sh2 + (ln0 + j)*FP + f4*4);
                a1[j] += xv.x*w1.x + xv.y*w1.y + xv.z*w1.z + xv.w*w1.w;
                a2[j] += xv.x*w2.x + xv.y*w2.y + xv.z*w2.z + xv.w*w2.w;
            }
        }
        float zz[8];
        #pragma unroll
        for (int j = 0; j < 8; j++) {
            int ln = ln0 + j;
            float rst = 1.f / (1.f + __expf(-a1[j]));
            zz[j]     = 1.f / (1.f + __expf(-a2[j]));
            srh2[ln*FP + 1 + u] = rst * h2v[j];
            if (u == 0) {
                srh2[ln*FP] = xinv[j];
                srh2[ln*FP + 65] = 0.f; srh2[ln*FP + 66] = 0.f; srh2[ln*FP + 67] = 0.f;
            }
        }
        __syncthreads();

        // phase 3: c = tanh([xin, reset*h2] @ W2 + b2)
        float cacc[8];
        #pragma unroll
        for (int j = 0; j < 8; j++) cacc[j] = sb2[u];
        #pragma unroll 4
        for (int f4 = 0; f4 < 17; f4++) {
            float4 w = w24[f4];
            #pragma unroll
            for (int j = 0; j < 8; j++) {
                float4 xv = *(const float4*)(srh2 + (ln0 + j)*FP + f4*4);
                cacc[j] += xv.x*w.x + xv.y*w.y + xv.z*w.z + xv.w*w.w;
            }
        }
        #pragma unroll
        for (int j = 0; j < 8; j++) {
            int node = base + ln0 + j;
            float cc = tanhf(cacc[j]);
            out[(size_t)node*Uu + u] = (1.f - zz[j]) * h2v[j] + zz[j] * cc;
        }
    }
}

// ---------------- launch ----------------
extern "C" void kernel_launch(void* const* d_in, const int* in_sizes, int n_in,
                              void* d_out, int out_size)
{
    const float* inputs = (const float*)d_in[0];
    const float* state  = (const float*)d_in[1];
    const int*   esrc   = (const int*)d_in[2];
    const int*   edst   = (const int*)d_in[3];
    const float* Wq = (const float*)d_in[4];
    const float* bq = (const float*)d_in[5];
    const float* Wk = (const float*)d_in[6];
    const float* bk = (const float*)d_in[7];
    const float* Wv = (const float*)d_in[8];
    const float* bv = (const float*)d_in[9];
    const float* Ws = (const float*)d_in[10];
    const float* bs = (const float*)d_in[11];
    const float* W1 = (const float*)d_in[12];
    const float* b1 = (const float*)d_in[13];
    const float* W2 = (const float*)d_in[14];
    const float* b2 = (const float*)d_in[15];
    float* out = (float*)d_out;

    const int SMEM_A = (3*64*FP + 192 + 32*FP) * (int)sizeof(float);
    const int SMEM_D = (4*64*FP + 256 + 3*32*FP) * (int)sizeof(float);

    cudaFuncSetAttribute(qkv_kernel, cudaFuncAttributeMaxDynamicSharedMemorySize, SMEM_A);
    cudaFuncSetAttribute(gru_kernel, cudaFuncAttributeMaxDynamicSharedMemorySize, SMEM_D);

    // CSR build
    zero_cnt_kernel<<<(Nn + 255)/256, 256>>>();
    hist_kernel<<<(Ee/4 + 255)/256, 256>>>(edst);
    scan_kernel<<<1, 1024>>>();
    scatter_kernel<<<(Ee/4 + 255)/256, 256>>>(edst, esrc);

    // projections
    qkv_kernel<<<444, 256, SMEM_A>>>(inputs, state, Wq, bq, Wk, bk, Wv, bv);

    // attention: one warp per (b, dst), 8 lanes per edge
    attn_kernel<<<(NODES*32 + 255)/256, 256>>>();

    // fused GRU
    gru_kernel<<<296, 256, SMEM_D>>>(inputs, state, Ws, bs, W1, b1, W2, b2, out);
}

// round 5
// speedup vs baseline: 2.0039x; 1.0400x over previous
#include <cuda_runtime.h>
#include <cuda_fp16.h>
#include <math.h>

#define Bb 4
#define Nn 20000
#define Uu 64
#define Ff 65
#define Ee 640000
#define NODES (Bb*Nn)
#define ATT_SCALE 0.125f
#define FP 68          // padded weight row stride (floats)
#define XS 36          // f-major x row stride (floats), mult of 4

typedef unsigned long long ull;

__device__ __forceinline__ ull pack2(float v) {
    ull r; asm("mov.b64 %0, {%1, %1};" : "=l"(r) : "f"(v)); return r;
}
__device__ __forceinline__ void fma2(ull &acc, ull x, ull w) {
    asm("fma.rn.f32x2 %0, %1, %2, %0;" : "+l"(acc) : "l"(x), "l"(w));
}
__device__ __forceinline__ float2 unpack2(ull v) {
    float2 f; asm("mov.b64 {%0, %1}, %2;" : "=f"(f.x), "=f"(f.y) : "l"(v)); return f;
}

// ---------------- device scratch (static, no runtime alloc) ----------------
__device__ __align__(16) __half g_qh[NODES*Uu];   // prescaled by ATT_SCALE
__device__ __align__(16) __half g_kh[NODES*Uu];
__device__ __align__(16) __half g_vh[NODES*Uu];
__device__ __align__(16) float  g_agg[NODES*Uu];
__device__ unsigned char g_mask[NODES];
__device__ int g_cnt[Nn];
__device__ int g_off[Nn];
__device__ int g_cur[Nn];
__device__ int g_srt[Ee];   // src ids sorted by dst (CSR payload)

// ---------------- CSR build ----------------
__global__ void zero_cnt_kernel() {
    int i = blockIdx.x * blockDim.x + threadIdx.x;
    if (i < Nn) g_cnt[i] = 0;
}

__global__ void hist_kernel(const int* __restrict__ edst) {
    int i = blockIdx.x * blockDim.x + threadIdx.x;
    if (i < Ee/4) {
        int4 d = ((const int4*)edst)[i];
        atomicAdd(&g_cnt[d.x], 1);
        atomicAdd(&g_cnt[d.y], 1);
        atomicAdd(&g_cnt[d.z], 1);
        atomicAdd(&g_cnt[d.w], 1);
    }
}

__global__ void scan_kernel() {
    __shared__ int sp[1024];
    int tid = threadIdx.x;
    int base = tid * 20;
    int s = 0;
    #pragma unroll
    for (int i = 0; i < 20; i++) {
        int idx = base + i;
        if (idx < Nn) s += g_cnt[idx];
    }
    sp[tid] = s;
    __syncthreads();
    for (int d = 1; d < 1024; d <<= 1) {
        int v = (tid >= d) ? sp[tid - d] : 0;
        __syncthreads();
        sp[tid] += v;
        __syncthreads();
    }
    int run = sp[tid] - s;   // exclusive prefix
    #pragma unroll
    for (int i = 0; i < 20; i++) {
        int idx = base + i;
        if (idx < Nn) {
            g_off[idx] = run;
            g_cur[idx] = run;
            run += g_cnt[idx];
        }
    }
}

__global__ void scatter_kernel(const int* __restrict__ edst,
                               const int* __restrict__ esrc) {
    int i = blockIdx.x * blockDim.x + threadIdx.x;
    if (i < Ee/4) {
        int4 d = ((const int4*)edst)[i];
        int4 s = ((const int4*)esrc)[i];
        int p0 = atomicAdd(&g_cur[d.x], 1); g_srt[p0] = s.x;
        int p1 = atomicAdd(&g_cur[d.y], 1); g_srt[p1] = s.y;
        int p2 = atomicAdd(&g_cur[d.z], 1); g_srt[p2] = s.z;
        int p3 = atomicAdd(&g_cur[d.w], 1); g_srt[p3] = s.w;
    }
}

// ---------------- QKV projection + mask (f32x2 packed FMA) ----------------
// x staged feature-major: sxT[f][node], 32 nodes per chunk. Two adjacent
// nodes form one f32x2 operand; weights broadcast-packed per (u,f).
__global__ void __launch_bounds__(256) qkv_kernel(
    const float* __restrict__ inputs, const float* __restrict__ state,
    const float* __restrict__ Wq, const float* __restrict__ bq,
    const float* __restrict__ Wk, const float* __restrict__ bk,
    const float* __restrict__ Wv, const float* __restrict__ bv)
{
    extern __shared__ float sm[];
    float* sWqT = sm;                  // 64*FP   (W[u][f], zero-padded f=65..67)
    float* sWkT = sWqT + 64*FP;
    float* sWvT = sWkT + 64*FP;
    float* sb   = sWvT + 64*FP;        // 192
    float* sxT  = sb + 192;            // 68*XS   (x[f][node])

    for (int i = threadIdx.x; i < Ff*Uu; i += 256) {
        int f = i >> 6, u = i & 63;
        sWqT[u*FP + f] = Wq[i];
        sWkT[u*FP + f] = Wk[i];
        sWvT[u*FP + f] = Wv[i];
    }
    for (int i = threadIdx.x; i < 192; i += 256) {
        int u = i & 63, p = i >> 6;    // pad f=65..67
        sWqT[u*FP + 65 + p] = 0.f;
        sWkT[u*FP + 65 + p] = 0.f;
        sWvT[u*FP + 65 + p] = 0.f;
    }
    if (threadIdx.x < 192) sb[threadIdx.x] =
        (threadIdx.x < 64) ? bq[threadIdx.x] :
        (threadIdx.x < 128) ? bk[threadIdx.x - 64] : bv[threadIdx.x - 128];
    if (threadIdx.x < 96) {            // zero pad rows 65..67 once
        int r = 65 + threadIdx.x / 32;
        sxT[r*XS + (threadIdx.x & 31)] = 0.f;
    }
    __syncthreads();

    int u = threadIdx.x & 63;
    int g = threadIdx.x >> 6;
    int ln0 = g * 8;
    const float4* wq4 = (const float4*)(sWqT + u*FP);
    const float4* wk4 = (const float4*)(sWkT + u*FP);
    const float4* wv4 = (const float4*)(sWvT + u*FP);

    for (int c = blockIdx.x; c < NODES/32; c += gridDim.x) {
        int base = c * 32;
        __syncthreads();
        // stage f-major: coalesced float4 reads, scalar transposed writes
        #pragma unroll
        for (int i = threadIdx.x; i < 512; i += 256) {
            int node = i >> 4, f4 = i & 15;
            float4 v = ((const float4*)state)[(size_t)(base + node)*16 + f4];
            sxT[(f4*4+0)*XS + node] = v.x;
            sxT[(f4*4+1)*XS + node] = v.y;
            sxT[(f4*4+2)*XS + node] = v.z;
            sxT[(f4*4+3)*XS + node] = v.w;
        }
        if (threadIdx.x < 32) {
            int node = base + threadIdx.x;
            sxT[64*XS + threadIdx.x] = inputs[node];
            g_mask[node] = (__ldg(&state[(size_t)node*Uu + 58]) != 0.f) ? 1 : 0;
        }
        __syncthreads();

        ull aq[4], ak[4], av[4];
        #pragma unroll
        for (int p = 0; p < 4; p++) { aq[p]=0ull; ak[p]=0ull; av[p]=0ull; }

        #pragma unroll 4
        for (int f4 = 0; f4 < 17; f4++) {
            float4 wq = wq4[f4], wk = wk4[f4], wv = wv4[f4];
            #pragma unroll
            for (int e = 0; e < 4; e++) {
                int f = f4*4 + e;
                ulonglong2 xab = *(const ulonglong2*)(sxT + f*XS + ln0);
                ulonglong2 xcd = *(const ulonglong2*)(sxT + f*XS + ln0 + 4);
                float wqe = (e==0)?wq.x:(e==1)?wq.y:(e==2)?wq.z:wq.w;
                float wke = (e==0)?wk.x:(e==1)?wk.y:(e==2)?wk.z:wk.w;
                float wve = (e==0)?wv.x:(e==1)?wv.y:(e==2)?wv.z:wv.w;
                ull wq2 = pack2(wqe), wk2 = pack2(wke), wv2 = pack2(wve);
                fma2(aq[0], xab.x, wq2); fma2(aq[1], xab.y, wq2);
                fma2(aq[2], xcd.x, wq2); fma2(aq[3], xcd.y, wq2);
                fma2(ak[0], xab.x, wk2); fma2(ak[1], xab.y, wk2);
                fma2(ak[2], xcd.x, wk2); fma2(ak[3], xcd.y, wk2);
                fma2(av[0], xab.x, wv2); fma2(av[1], xab.y, wv2);
                fma2(av[2], xcd.x, wv2); fma2(av[3], xcd.y, wv2);
            }
        }
        float bqv = sb[u], bkv = sb[64+u], bvv = sb[128+u];
        #pragma unroll
        for (int p = 0; p < 4; p++) {
            float2 fq = unpack2(aq[p]);
            float2 fk = unpack2(ak[p]);
            float2 fv = unpack2(av[p]);
            size_t i0 = (size_t)(base + ln0 + 2*p)*Uu + u;
            g_qh[i0]      = __float2half_rn((fq.x + bqv) * ATT_SCALE);
            g_qh[i0 + Uu] = __float2half_rn((fq.y + bqv) * ATT_SCALE);
            g_kh[i0]      = __float2half_rn(fk.x + bkv);
            g_kh[i0 + Uu] = __float2half_rn(fk.y + bkv);
            g_vh[i0]      = __float2half_rn(fv.x + bvv);
            g_vh[i0 + Uu] = __float2half_rn(fv.y + bvv);
        }
    }
}

// ---------------- attention: one warp per (b, dst), 8 lanes per edge -------
__device__ __forceinline__ void ld_h8(const __half* p, float2 f[4]) {
    uint4 r = *reinterpret_cast<const uint4*>(p);
    f[0] = __half22float2(*reinterpret_cast<__half2*>(&r.x));
    f[1] = __half22float2(*reinterpret_cast<__half2*>(&r.y));
    f[2] = __half22float2(*reinterpret_cast<__half2*>(&r.z));
    f[3] = __half22float2(*reinterpret_cast<__half2*>(&r.w));
}

__global__ void __launch_bounds__(256) attn_kernel() {
    int gw = (blockIdx.x * blockDim.x + threadIdx.x) >> 5;
    if (gw >= NODES) return;
    if (!g_mask[gw]) return;

    int lane = threadIdx.x & 31;
    int grp  = lane >> 3;     // edge slot 0..3
    int sub  = lane & 7;      // dim group: dims [sub*8, sub*8+8)
    int b = gw / Nn;
    int n = gw - b * Nn;

    size_t rowbase = (size_t)gw * Uu;
    float2 q[4];
    ld_h8(g_qh + rowbase + sub*8, q);

    int off = g_off[n];
    int deg = g_cnt[n];
    int end = off + deg;
    const __half* kb = g_kh + (size_t)b * Nn * Uu;
    const __half* vb = g_vh + (size_t)b * Nn * Uu;
    const unsigned char* mk = g_mask + b * Nn;

    float2 acc[4] = {{0,0},{0,0},{0,0},{0,0}};
    float den = 0.f;

    // prefetch first src ids
    int sA = 0, sB = 0; bool vA = false, vB = false;
    if (off < end) {
        int eA = off + grp, eB = off + 4 + grp;
        vA = eA < end; vB = eB < end;
        sA = __ldg(&g_srt[vA ? eA : off]);
        sB = __ldg(&g_srt[vB ? eB : off]);
    }

    for (int t = off; t < end; t += 8) {
        int s0 = sA, s1 = sB;
        bool val0 = vA, val1 = vB;
        int tn = t + 8;
        if (tn < end) {          // prefetch next iteration's src ids
            int eA = tn + grp, eB = tn + 4 + grp;
            vA = eA < end; vB = eB < end;
            sA = __ldg(&g_srt[vA ? eA : off]);
            sB = __ldg(&g_srt[vB ? eB : off]);
        }

        // issue all loads up-front (mask, k, v)
        unsigned m0 = mk[s0], m1 = mk[s1];
        float2 k0[4], k1[4], v0[4], v1[4];
        ld_h8(kb + (size_t)s0 * Uu + sub*8, k0);
        ld_h8(kb + (size_t)s1 * Uu + sub*8, k1);
        ld_h8(vb + (size_t)s0 * Uu + sub*8, v0);
        ld_h8(vb + (size_t)s1 * Uu + sub*8, v1);

        float p0 = k0[0].x*q[0].x + k0[0].y*q[0].y
                 + k0[1].x*q[1].x + k0[1].y*q[1].y
                 + k0[2].x*q[2].x + k0[2].y*q[2].y
                 + k0[3].x*q[3].x + k0[3].y*q[3].y;
        float p1 = k1[0].x*q[0].x + k1[0].y*q[0].y
                 + k1[1].x*q[1].x + k1[1].y*q[1].y
                 + k1[2].x*q[2].x + k1[2].y*q[2].y
                 + k1[3].x*q[3].x + k1[3].y*q[3].y;
        #pragma unroll
        for (int d = 1; d < 8; d <<= 1) {
            p0 += __shfl_xor_sync(0xffffffffu, p0, d);
            p1 += __shfl_xor_sync(0xffffffffu, p1, d);
        }
        float w0 = (val0 && m0) ? __expf(p0) : 0.f;
        float w1 = (val1 && m1) ? __expf(p1) : 0.f;

        #pragma unroll
        for (int i = 0; i < 4; i++) {
            acc[i].x += w0 * v0[i].x + w1 * v1[i].x;
            acc[i].y += w0 * v0[i].y + w1 * v1[i].y;
        }
        den += w0 + w1;
    }

    // cross-group reduce (groups 0..3 hold disjoint edge subsets)
    #pragma unroll
    for (int d = 8; d < 32; d <<= 1) {
        #pragma unroll
        for (int i = 0; i < 4; i++) {
            acc[i].x += __shfl_xor_sync(0xffffffffu, acc[i].x, d);
            acc[i].y += __shfl_xor_sync(0xffffffffu, acc[i].y, d);
        }
        den += __shfl_xor_sync(0xffffffffu, den, d);
    }

    if (lane < 8) {
        float inv = (den > 0.f) ? 1.f / fmaxf(den, 1e-16f) : 0.f;
        float4* op = (float4*)(g_agg + rowbase + sub * 8);
        op[0] = make_float4(acc[0].x*inv, acc[0].y*inv, acc[1].x*inv, acc[1].y*inv);
        op[1] = make_float4(acc[2].x*inv, acc[2].y*inv, acc[3].x*inv, acc[3].y*inv);
    }
}

// ---------------- fused GRU epilogue (f32x2 packed FMA) ----------------
__global__ void __launch_bounds__(256) gru_kernel(
    const float* __restrict__ inputs, const float* __restrict__ state,
    const float* __restrict__ Ws, const float* __restrict__ bs,
    const float* __restrict__ W1, const float* __restrict__ b1,
    const float* __restrict__ W2, const float* __restrict__ b2,
    float* __restrict__ out)
{
    extern __shared__ float sm[];
    float* sWsT  = sm;                   // 64*FP
    float* sW1aT = sWsT  + 64*FP;        // cols 0..63
    float* sW1bT = sW1aT + 64*FP;        // cols 64..127
    float* sW2T  = sW1bT + 64*FP;
    float* sbs = sW2T + 64*FP;           // 64
    float* sb1 = sbs + 64;               // 128
    float* sb2 = sb1 + 128;              // 64
    float* sxT   = sb2 + 64;             // 68*XS  x = [h, xin] f-major
    float* sh2T  = sxT  + 68*XS;         // 68*XS  cat1 = [xin, h2]
    float* srh2T = sh2T + 68*XS;         // 68*XS  [xin, reset*h2]

    for (int i = threadIdx.x; i < Ff*Uu; i += 256) {
        int f = i >> 6, u = i & 63;
        sWsT[u*FP + f] = Ws[i];
        sW2T[u*FP + f] = W2[i];
    }
    for (int i = threadIdx.x; i < Ff*128; i += 256) {
        int f = i >> 7, c = i & 127;
        if (c < 64) sW1aT[c*FP + f] = W1[i];
        else        sW1bT[(c-64)*FP + f] = W1[i];
    }
    for (int i = threadIdx.x; i < 192; i += 256) {
        int u = i & 63, p = i >> 6;
        sWsT[u*FP + 65 + p] = 0.f;
        sW1aT[u*FP + 65 + p] = 0.f;
        sW1bT[u*FP + 65 + p] = 0.f;
        sW2T[u*FP + 65 + p] = 0.f;
    }
    if (threadIdx.x < 64)  sbs[threadIdx.x] = bs[threadIdx.x];
    if (threadIdx.x < 128) sb1[threadIdx.x] = b1[threadIdx.x];
    if (threadIdx.x < 64)  sb2[threadIdx.x] = b2[threadIdx.x];
    if (threadIdx.x < 96) {              // zero pad rows 65..67 once
        int r = 65 + threadIdx.x / 32;
        int nl = threadIdx.x & 31;
        sxT[r*XS + nl] = 0.f;
        sh2T[r*XS + nl] = 0.f;
        srh2T[r*XS + nl] = 0.f;
    }
    __syncthreads();

    int u = threadIdx.x & 63;
    int g = threadIdx.x >> 6;
    int ln0 = g * 8;
    const float4* ws4  = (const float4*)(sWsT  + u*FP);
    const float4* w1a4 = (const float4*)(sW1aT + u*FP);
    const float4* w1b4 = (const float4*)(sW1bT + u*FP);
    const float4* w24  = (const float4*)(sW2T  + u*FP);

    for (int c = blockIdx.x; c < NODES/32; c += gridDim.x) {
        int base = c * 32;
        __syncthreads();
        #pragma unroll
        for (int i = threadIdx.x; i < 512; i += 256) {
            int node = i >> 4, f4 = i & 15;
            float4 v = ((const float4*)state)[(size_t)(base + node)*16 + f4];
            sxT[(f4*4+0)*XS + node] = v.x;
            sxT[(f4*4+1)*XS + node] = v.y;
            sxT[(f4*4+2)*XS + node] = v.z;
            sxT[(f4*4+3)*XS + node] = v.w;
        }
        if (threadIdx.x < 32) {
            sxT[64*XS + threadIdx.x] = inputs[base + threadIdx.x];
        }
        __syncthreads();

        // phase 1: s = x @ Ws
        ull acc[4]; 
        #pragma unroll
        for (int p = 0; p < 4; p++) acc[p] = 0ull;
        #pragma unroll 4
        for (int f4 = 0; f4 < 17; f4++) {
            float4 w = ws4[f4];
            #pragma unroll
            for (int e = 0; e < 4; e++) {
                int f = f4*4 + e;
                ulonglong2 xab = *(const ulonglong2*)(sxT + f*XS + ln0);
                ulonglong2 xcd = *(const ulonglong2*)(sxT + f*XS + ln0 + 4);
                float we = (e==0)?w.x:(e==1)?w.y:(e==2)?w.z:w.w;
                ull w2 = pack2(we);
                fma2(acc[0], xab.x, w2); fma2(acc[1], xab.y, w2);
                fma2(acc[2], xcd.x, w2); fma2(acc[3], xcd.y, w2);
            }
        }
        float sres[8];
        #pragma unroll
        for (int p = 0; p < 4; p++) {
            float2 f2 = unpack2(acc[p]);
            sres[2*p] = f2.x; sres[2*p+1] = f2.y;
        }

        float h2v[8], xinv[8];
        float bsu = sbs[u];
        #pragma unroll
        for (int j = 0; j < 8; j++) {
            int nl = ln0 + j;
            int node = base + nl;
            float hv  = sxT[u*XS + nl];
            xinv[j]   = sxT[64*XS + nl];
            bool msk  = (sxT[58*XS + nl] != 0.f);
            float av  = g_agg[(size_t)node*Uu + u];
            float h2  = msk ? (av + sres[j] + bsu) : hv;
            h2v[j] = h2;
            sh2T[(1+u)*XS + nl] = h2;
            if (u == 0) sh2T[nl] = xinv[j];
        }
        __syncthreads();

        // phase 2: value = sigmoid(cat1 @ W1 + b1)
        ull a1[4], a2[4];
        ull b1a = pack2(sb1[u]), b1b = pack2(sb1[64+u]);
        #pragma unroll
        for (int p = 0; p < 4; p++) { a1[p] = b1a; a2[p] = b1b; }
        #pragma unroll 4
        for (int f4 = 0; f4 < 17; f4++) {
            float4 wa = w1a4[f4], wb = w1b4[f4];
            #pragma unroll
            for (int e = 0; e < 4; e++) {
                int f = f4*4 + e;
                ulonglong2 xab = *(const ulonglong2*)(sh2T + f*XS + ln0);
                ulonglong2 xcd = *(const ulonglong2*)(sh2T + f*XS + ln0 + 4);
                float wae = (e==0)?wa.x:(e==1)?wa.y:(e==2)?wa.z:wa.w;
                float wbe = (e==0)?wb.x:(e==1)?wb.y:(e==2)?wb.z:wb.w;
                ull wa2 = pack2(wae), wb2 = pack2(wbe);
                fma2(a1[0], xab.x, wa2); fma2(a1[1], xab.y, wa2);
                fma2(a1[2], xcd.x, wa2); fma2(a1[3], xcd.y, wa2);
                fma2(a2[0], xab.x, wb2); fma2(a2[1], xab.y, wb2);
                fma2(a2[2], xcd.x, wb2); fma2(a2[3], xcd.y, wb2);
            }
        }
        float zz[8];
        #pragma unroll
        for (int p = 0; p < 4; p++) {
            float2 f1 = unpack2(a1[p]);
            float2 f2 = unpack2(a2[p]);
            float rst0 = 1.f / (1.f + __expf(-f1.x));
            float rst1 = 1.f / (1.f + __expf(-f1.y));
            zz[2*p]   = 1.f / (1.f + __expf(-f2.x));
            zz[2*p+1] = 1.f / (1.f + __expf(-f2.y));
            int nl0 = ln0 + 2*p;
            srh2T[(1+u)*XS + nl0]     = rst0 * h2v[2*p];
            srh2T[(1+u)*XS + nl0 + 1] = rst1 * h2v[2*p+1];
            if (u == 0) {
                srh2T[nl0] = xinv[2*p];
                srh2T[nl0 + 1] = xinv[2*p+1];
            }
        }
        __syncthreads();

        // phase 3: c = tanh([xin, reset*h2] @ W2 + b2)
        ull cacc[4];
        ull b2p = pack2(sb2[u]);
        #pragma unroll
        for (int p = 0; p < 4; p++) cacc[p] = b2p;
        #pragma unroll 4
        for (int f4 = 0; f4 < 17; f4++) {
            float4 w = w24[f4];
            #pragma unroll
            for (int e = 0; e < 4; e++) {
                int f = f4*4 + e;
                ulonglong2 xab = *(const ulonglong2*)(srh2T + f*XS + ln0);
                ulonglong2 xcd = *(const ulonglong2*)(srh2T + f*XS + ln0 + 4);
                float we = (e==0)?w.x:(e==1)?w.y:(e==2)?w.z:w.w;
                ull w2 = pack2(we);
                fma2(cacc[0], xab.x, w2); fma2(cacc[1], xab.y, w2);
                fma2(cacc[2], xcd.x, w2); fma2(cacc[3], xcd.y, w2);
            }
        }
        #pragma unroll
        for (int p = 0; p < 4; p++) {
            float2 f2 = unpack2(cacc[p]);
            int j0 = 2*p;
            float cc0 = tanhf(f2.x), cc1 = tanhf(f2.y);
            size_t i0 = (size_t)(base + ln0 + j0)*Uu + u;
            out[i0]      = (1.f - zz[j0])   * h2v[j0]   + zz[j0]   * cc0;
            out[i0 + Uu] = (1.f - zz[j0+1]) * h2v[j0+1] + zz[j0+1] * cc1;
        }
    }
}

// ---------------- launch ----------------
extern "C" void kernel_launch(void* const* d_in, const int* in_sizes, int n_in,
                              void* d_out, int out_size)
{
    const float* inputs = (const float*)d_in[0];
    const float* state  = (const float*)d_in[1];
    const int*   esrc   = (const int*)d_in[2];
    const int*   edst   = (const int*)d_in[3];
    const float* Wq = (const float*)d_in[4];
    const float* bq = (const float*)d_in[5];
    const float* Wk = (const float*)d_in[6];
    const float* bk = (const float*)d_in[7];
    const float* Wv = (const float*)d_in[8];
    const float* bv = (const float*)d_in[9];
    const float* Ws = (const float*)d_in[10];
    const float* bs = (const float*)d_in[11];
    const float* W1 = (const float*)d_in[12];
    const float* b1 = (const float*)d_in[13];
    const float* W2 = (const float*)d_in[14];
    const float* b2 = (const float*)d_in[15];
    float* out = (float*)d_out;

    const int SMEM_A = (3*64*FP + 192 + 68*XS) * (int)sizeof(float);
    const int SMEM_D = (4*64*FP + 256 + 3*68*XS) * (int)sizeof(float);

    cudaFuncSetAttribute(qkv_kernel, cudaFuncAttributeMaxDynamicSharedMemorySize, SMEM_A);
    cudaFuncSetAttribute(gru_kernel, cudaFuncAttributeMaxDynamicSharedMemorySize, SMEM_D);

    // CSR build
    zero_cnt_kernel<<<(Nn + 255)/256, 256>>>();
    hist_kernel<<<(Ee/4 + 255)/256, 256>>>(edst);
    scan_kernel<<<1, 1024>>>();
    scatter_kernel<<<(Ee/4 + 255)/256, 256>>>(edst, esrc);

    // projections
    qkv_kernel<<<444, 256, SMEM_A>>>(inputs, state, Wq, bq, Wk, bk, Wv, bv);

    // attention: one warp per (b, dst), 8 lanes per edge
    attn_kernel<<<(NODES*32 + 255)/256, 256>>>();

    // fused GRU
    gru_kernel<<<296, 256, SMEM_D>>>(inputs, state, Ws, bs, W1, b1, W2, b2, out);
}